// round 14
// baseline (speedup 1.0000x reference)
#include <cuda_runtime.h>
#include <cuda_bf16.h>
#include <cuda_fp16.h>
#include <stdint.h>

#define DD 128
#define LL 200

// ---------------- device scratch (static globals: allocation-free) ----------
__device__ __nv_bfloat16 g_kWh[(size_t)100001 * DD];  // (item_emb @ Wk) in bf16
__device__ __half        g_ieh[(size_t)100001 * DD];  // item_emb shadow, fp16
__device__ __nv_bfloat16 g_WkT[DD * DD];              // Wk^T, bf16
__device__ __nv_bfloat16 g_WqT[DD * DD];              // Wq^T, bf16
__device__ float g_qWb[(size_t)8192 * DD];            // user_emb[uidx]@Wq + b_att
__device__ float g_klsum[8192];
__device__ float g_nvalid[8192];
__device__ int   g_ctr;                               // self-resetting counter

__device__ __forceinline__ float tanh_hw(float x) {
    float t; asm("tanh.approx.f32 %0, %1;" : "=f"(t) : "f"(x)); return t;
}

// ---------------- kernel 0: transpose Wk, Wq -> bf16 ------------------------
__global__ __launch_bounds__(256) void wkt_kernel(
    const float* __restrict__ Wk, const float* __restrict__ Wq)
{
    __shared__ float tile[32][33];
    int which = blockIdx.x >> 4;
    int bi = blockIdx.x & 15;
    const float* src = which ? Wq : Wk;
    __nv_bfloat16* dst = which ? g_WqT : g_WkT;
    int bx = (bi & 3) * 32;             // n tile
    int by = (bi >> 2) * 32;            // k tile
    int tx = threadIdx.x & 31, ty = threadIdx.x >> 5;
#pragma unroll
    for (int j = 0; j < 4; ++j)
        tile[ty + j * 8][tx] = src[(by + ty + j * 8) * DD + bx + tx];
    __syncthreads();
#pragma unroll
    for (int j = 0; j < 4; ++j)
        dst[(bx + ty + j * 8) * DD + by + tx] =
            __float2bfloat16(tile[tx][ty + j * 8]);
}

// ---------------- bf16 mma tile: C[128x128] = A @ W^T -----------------------
#define TSH 136
#define GEMM_SMEM_BYTES (2 * 128 * TSH * 2)

template <bool GATHER, bool OUT_BF16>
__device__ __forceinline__ void mma_bf16_tile(
    const float* __restrict__ Arows, const int* __restrict__ gidx,
    const __nv_bfloat16* __restrict__ WT, const float* __restrict__ bias,
    void* __restrict__ Cout, size_t base, int n_rows, __nv_bfloat16* sh)
{
    __nv_bfloat16* As = sh;                 // [128][TSH]
    __nv_bfloat16* Bs = sh + 128 * TSH;     // [128][TSH] (n-major)
    int tid = threadIdx.x, lane = tid & 31, warp = tid >> 5;

    const float4* A4 = reinterpret_cast<const float4*>(Arows);
#pragma unroll
    for (int j = 0; j < 16; ++j) {
        int f = tid + j * 256;              // 0..4095
        int m = f >> 5, kc = f & 31;
        size_t gi = base + m; if (gi >= (size_t)n_rows) gi = n_rows - 1;
        if (GATHER) gi = (size_t)gidx[gi];
        float4 v = A4[gi * 32 + kc];
        // kw path: persist fp16 shadow of the ORIGINAL fp32 values (ctx table)
        if (OUT_BF16) {
            size_t go = base + m;
            if (go < (size_t)n_rows) {
                __half2 hlo = __floats2half2_rn(v.x, v.y);
                __half2 hhi = __floats2half2_rn(v.z, v.w);
                *reinterpret_cast<uint2*>(&g_ieh[go * DD + kc * 4]) =
                    make_uint2(*reinterpret_cast<uint32_t*>(&hlo),
                               *reinterpret_cast<uint32_t*>(&hhi));
            }
        }
        __nv_bfloat162 lo = __floats2bfloat162_rn(v.x, v.y);
        __nv_bfloat162 hi = __floats2bfloat162_rn(v.z, v.w);
        *reinterpret_cast<uint2*>(&As[m * TSH + kc * 4]) =
            make_uint2(*reinterpret_cast<uint32_t*>(&lo),
                       *reinterpret_cast<uint32_t*>(&hi));
    }
    const uint4* W4 = reinterpret_cast<const uint4*>(WT);
#pragma unroll
    for (int j = 0; j < 8; ++j) {
        int f = tid + j * 256;              // 0..2047
        int n = f >> 4, kc = f & 15;
        *reinterpret_cast<uint4*>(&Bs[n * TSH + kc * 8]) = W4[f];
    }
    __syncthreads();

    int gq = lane >> 2, tg2 = (lane & 3) * 2;
    int mrow = (warp >> 1) * 32;
    int ncol = (warp & 1) * 64;

    float c[2][8][4];
#pragma unroll
    for (int mi = 0; mi < 2; ++mi)
#pragma unroll
        for (int nt = 0; nt < 8; ++nt)
#pragma unroll
            for (int i = 0; i < 4; ++i) c[mi][nt][i] = 0.f;

#pragma unroll
    for (int ks = 0; ks < 8; ++ks) {
        int k0 = ks * 16;
        uint32_t bq[8][2];
#pragma unroll
        for (int nt = 0; nt < 8; ++nt) {
            const __nv_bfloat16* bp = &Bs[(ncol + nt * 8 + gq) * TSH + k0 + tg2];
            bq[nt][0] = *reinterpret_cast<const uint32_t*>(bp);
            bq[nt][1] = *reinterpret_cast<const uint32_t*>(bp + 8);
        }
#pragma unroll
        for (int mi = 0; mi < 2; ++mi) {
            const __nv_bfloat16* ap0 = &As[(mrow + mi * 16 + gq) * TSH + k0 + tg2];
            const __nv_bfloat16* ap1 = ap0 + 8 * TSH;
            uint32_t a0 = *reinterpret_cast<const uint32_t*>(ap0);
            uint32_t a1 = *reinterpret_cast<const uint32_t*>(ap1);
            uint32_t a2 = *reinterpret_cast<const uint32_t*>(ap0 + 8);
            uint32_t a3 = *reinterpret_cast<const uint32_t*>(ap1 + 8);
#pragma unroll
            for (int nt = 0; nt < 8; ++nt) {
                asm volatile(
                    "mma.sync.aligned.m16n8k16.row.col.f32.bf16.bf16.f32 "
                    "{%0,%1,%2,%3}, {%4,%5,%6,%7}, {%8,%9}, {%0,%1,%2,%3};"
                    : "+f"(c[mi][nt][0]), "+f"(c[mi][nt][1]),
                      "+f"(c[mi][nt][2]), "+f"(c[mi][nt][3])
                    : "r"(a0), "r"(a1), "r"(a2), "r"(a3),
                      "r"(bq[nt][0]), "r"(bq[nt][1]));
            }
        }
    }

#pragma unroll
    for (int mi = 0; mi < 2; ++mi) {
        size_t g0 = base + mrow + mi * 16 + gq;
        bool ok0 = g0 < (size_t)n_rows, ok1 = (g0 + 8) < (size_t)n_rows;
#pragma unroll
        for (int nt = 0; nt < 8; ++nt) {
            int col = ncol + nt * 8 + tg2;
            if (OUT_BF16) {
                __nv_bfloat16* Ch = reinterpret_cast<__nv_bfloat16*>(Cout);
                if (ok0) *reinterpret_cast<__nv_bfloat162*>(&Ch[g0 * DD + col])
                             = __floats2bfloat162_rn(c[mi][nt][0], c[mi][nt][1]);
                if (ok1) *reinterpret_cast<__nv_bfloat162*>(&Ch[(g0 + 8) * DD + col])
                             = __floats2bfloat162_rn(c[mi][nt][2], c[mi][nt][3]);
            } else {
                float* Cf = reinterpret_cast<float*>(Cout);
                float bx = __ldg(&bias[col]);
                float by = __ldg(&bias[col + 1]);
                if (ok0) *reinterpret_cast<float2*>(&Cf[g0 * DD + col])
                             = make_float2(c[mi][nt][0] + bx, c[mi][nt][1] + by);
                if (ok1) *reinterpret_cast<float2*>(&Cf[(g0 + 8) * DD + col])
                             = make_float2(c[mi][nt][2] + bx, c[mi][nt][3] + by);
            }
        }
    }
}

// ---------------- kernel 1: merged kW + qW GEMMs ----------------------------
__global__ __launch_bounds__(256, 2) void gemm_kernel(
    const float* __restrict__ item_emb, const float* __restrict__ user_emb,
    const float* __restrict__ b_att, const int* __restrict__ user_idx,
    int n_rows, int B, int kwBlocks)
{
    extern __shared__ __nv_bfloat16 sh[];
    if ((int)blockIdx.x < kwBlocks) {
        mma_bf16_tile<false, true>(item_emb, nullptr, g_WkT, nullptr, g_kWh,
                                   (size_t)blockIdx.x * 128, n_rows, sh);
    } else {
        mma_bf16_tile<true, false>(user_emb, user_idx, g_WqT, b_att, g_qWb,
                                   (size_t)(blockIdx.x - kwBlocks) * 128, B, sh);
    }
}

// ---------------- threefry2x32 (JAX-compatible) -----------------------------
__device__ __forceinline__ uint32_t rotl32(uint32_t x, int r) {
    return (x << r) | (x >> (32 - r));
}
__device__ __forceinline__ uint32_t threefry32(uint32_t k0, uint32_t k1,
                                               uint32_t x0, uint32_t x1) {
    uint32_t ks2 = k0 ^ k1 ^ 0x1BD11BDAu;
    x0 += k0; x1 += k1;
#define TFR(r) { x0 += x1; x1 = rotl32(x1, r); x1 ^= x0; }
    TFR(13) TFR(15) TFR(26) TFR(6)   x0 += k1;  x1 += ks2 + 1u;
    TFR(17) TFR(29) TFR(16) TFR(24)  x0 += ks2; x1 += k0 + 2u;
    TFR(13) TFR(15) TFR(26) TFR(6)   x0 += k0;  x1 += k1 + 3u;
    TFR(17) TFR(29) TFR(16) TFR(24)  x0 += k1;  x1 += ks2 + 4u;
    TFR(13) TFR(15) TFR(26) TFR(6)   x0 += ks2; x1 += k0 + 5u;
#undef TFR
    return x0 ^ x1;
}
__device__ __forceinline__ float jax_normal_from_bits(uint32_t bits) {
    float f = __uint_as_float((bits >> 9) | 0x3F800000u) - 1.0f;
    const float lo = -0.99999994f;
    float u = fmaf(f, 1.0f - lo, lo);
    u = fmaxf(lo, u);
    return 1.41421356f * erfinvf(u);
}

// ---------------- fused multi-value block reductions (128 threads) ----------
__device__ __forceinline__ void block_sum2(float& a, float& b, float* sR) {
#pragma unroll
    for (int o = 16; o; o >>= 1) {
        a += __shfl_xor_sync(0xffffffffu, a, o);
        b += __shfl_xor_sync(0xffffffffu, b, o);
    }
    int warp = threadIdx.x >> 5;
    __syncthreads();
    if ((threadIdx.x & 31) == 0) { sR[warp] = a; sR[4 + warp] = b; }
    __syncthreads();
    a = (sR[0] + sR[1]) + (sR[2] + sR[3]);
    b = (sR[4] + sR[5]) + (sR[6] + sR[7]);
}
__device__ __forceinline__ void block_sum3(float& a, float& b, float& c, float* sR) {
#pragma unroll
    for (int o = 16; o; o >>= 1) {
        a += __shfl_xor_sync(0xffffffffu, a, o);
        b += __shfl_xor_sync(0xffffffffu, b, o);
        c += __shfl_xor_sync(0xffffffffu, c, o);
    }
    int warp = threadIdx.x >> 5;
    __syncthreads();
    if ((threadIdx.x & 31) == 0) { sR[warp] = a; sR[4 + warp] = b; sR[8 + warp] = c; }
    __syncthreads();
    a = (sR[0] + sR[1]) + (sR[2] + sR[3]);
    b = (sR[4] + sR[5]) + (sR[6] + sR[7]);
    c = (sR[8] + sR[9]) + (sR[10] + sR[11]);
}
__device__ __forceinline__ void block_sum4(float& a, float& b, float& c, float& d,
                                           float* sR) {
#pragma unroll
    for (int o = 16; o; o >>= 1) {
        a += __shfl_xor_sync(0xffffffffu, a, o);
        b += __shfl_xor_sync(0xffffffffu, b, o);
        c += __shfl_xor_sync(0xffffffffu, c, o);
        d += __shfl_xor_sync(0xffffffffu, d, o);
    }
    int warp = threadIdx.x >> 5;
    __syncthreads();
    if ((threadIdx.x & 31) == 0) {
        sR[warp] = a; sR[4 + warp] = b; sR[8 + warp] = c; sR[12 + warp] = d;
    }
    __syncthreads();
    a = (sR[0]  + sR[1])  + (sR[2]  + sR[3]);
    b = (sR[4]  + sR[5])  + (sR[6]  + sR[7]);
    c = (sR[8]  + sR[9])  + (sR[10] + sR[11]);
    d = (sR[12] + sR[13]) + (sR[14] + sR[15]);
}
__device__ __forceinline__ float block_sum1(float v, float* sR) {
#pragma unroll
    for (int o = 16; o; o >>= 1) v += __shfl_xor_sync(0xffffffffu, v, o);
    __syncthreads();
    if ((threadIdx.x & 31) == 0) sR[threadIdx.x >> 5] = v;
    __syncthreads();
    return (sR[0] + sR[1]) + (sR[2] + sR[3]);
}

// ---------------- kernel 2: fused BAM + epilogue + last-block KL ------------
__global__ __launch_bounds__(128, 16) void main_kernel(
    const float* __restrict__ user_emb, const float* __restrict__ item_emb,
    const float* __restrict__ v_att,
    const float* __restrict__ ln_u_g,   const float* __restrict__ ln_u_b,
    const float* __restrict__ ln_i_g,   const float* __restrict__ ln_i_b,
    const float* __restrict__ pred_W,   const float* __restrict__ pred_b,
    const int*   __restrict__ user_hist,const int*  __restrict__ user_idx,
    const int*   __restrict__ item_idx, float* __restrict__ out, int pad_id,
    int B, int out_idx)
{
    __shared__ float sQ[DD];
    __shared__ int   sOffH[LL], sMask[LL];     // half-table byte offset r*256
    __shared__ float sS[LL], sW1[LL], sW2[LL]; // sS holds exp(s) (0 if masked)
    __shared__ float sRed[16];
    __shared__ int   sLast;

    int b = blockIdx.x, tid = threadIdx.x;
    int u = user_idx[b], t = item_idx[b];

    float cnt_t = 0.f;
    for (int l = tid; l < LL; l += 128) {
        int r = user_hist[(size_t)u * LL + l];
        sOffH[l] = r << 8;                     // r * 128 * 2 bytes
        int mk = (r != t) && (r != pad_id);
        sMask[l] = mk;
        cnt_t += (float)mk;
    }
    sQ[tid] = user_emb[(size_t)u * DD + tid];
    __syncthreads();

    int lane = tid & 31, warp = tid >> 5;

    // ---- scores+exp fused, branch-free: warp = 2 l/iter, 16 lanes x 8 dims.
    float esum_t = 0.f;
    {
        int half = lane >> 4, hl = lane & 15;
        int d0 = hl * 8;
        const float* qp = &g_qWb[(size_t)b * DD + d0];
        float4 qa = *reinterpret_cast<const float4*>(qp);
        float4 qb = *reinterpret_cast<const float4*>(qp + 4);
        float4 va = __ldg(reinterpret_cast<const float4*>(&v_att[d0]));
        float4 vb = __ldg(reinterpret_cast<const float4*>(&v_att[d0 + 4]));
        const char* kb = reinterpret_cast<const char*>(g_kWh) + d0 * 2;
        int lbase = warp * 2 + half;
#pragma unroll 5
        for (int i = 0; i < 25; ++i) {
            int l = lbase + i * 8;
            uint4 kv = __ldg(reinterpret_cast<const uint4*>(
                kb + (uint32_t)sOffH[l]));
            float2 f0 = __bfloat1622float2(*reinterpret_cast<__nv_bfloat162*>(&kv.x));
            float2 f1 = __bfloat1622float2(*reinterpret_cast<__nv_bfloat162*>(&kv.y));
            float2 f2 = __bfloat1622float2(*reinterpret_cast<__nv_bfloat162*>(&kv.z));
            float2 f3 = __bfloat1622float2(*reinterpret_cast<__nv_bfloat162*>(&kv.w));
            float p =      tanh_hw(qa.x + f0.x) * va.x;
            p = fmaf(tanh_hw(qa.y + f0.y), va.y, p);
            p = fmaf(tanh_hw(qa.z + f1.x), va.z, p);
            p = fmaf(tanh_hw(qa.w + f1.y), va.w, p);
            p = fmaf(tanh_hw(qb.x + f2.x), vb.x, p);
            p = fmaf(tanh_hw(qb.y + f2.y), vb.y, p);
            p = fmaf(tanh_hw(qb.z + f3.x), vb.z, p);
            p = fmaf(tanh_hw(qb.w + f3.y), vb.w, p);
#pragma unroll
            for (int o = 8; o; o >>= 1) p += __shfl_xor_sync(0xffffffffu, p, o);
            float e = __expf(p * 0.25f);
            e = sMask[l] ? e : 0.f;
            if (hl == 0) { sS[l] = e; esum_t += e; }
        }
    }
    float esum = esum_t, cnt = cnt_t;
    block_sum2(esum, cnt, sRed);
    float nv   = fmaxf(cnt, 1.f);
    float mu_p = -__logf(nv);
    float invE = 1.f / esum;

    // ---- sampled weights (two draws, shared alpha) + KL, branch-free ----
    float klacc = 0.f, ws1 = 0.f, ws2 = 0.f;
    uint32_t b200 = (uint32_t)b * LL;
    for (int l = tid; l < LL; l += 128) {
        int   mk = sMask[l];
        float a  = fmaf(sS[l], invE, 1e-24f);
        float mu = __logf(a);
        float dd = mu - mu_p;
        klacc += mk ? (1.8075851f + dd * dd * 0.5f) : 0.f;
        uint32_t idx = b200 + (uint32_t)l;
        float e1 = jax_normal_from_bits(threefry32(0u, 1u, 0u, idx));
        float e2 = jax_normal_from_bits(threefry32(0u, 2u, 0u, idx));
        float w1 = mk ? a * __expf(0.1f * e1) : 0.f;
        float w2 = mk ? a * __expf(0.1f * e2) : 0.f;
        sW1[l] = w1; sW2[l] = w2; ws1 += w1; ws2 += w2;
    }
    block_sum3(klacc, ws1, ws2, sRed);
    if (tid == 0) { g_klsum[b] = klacc; g_nvalid[b] = cnt; }
    float i1 = 1.f / (ws1 + 1e-12f), i2 = 1.f / (ws2 + 1e-12f);

    // ---- ctx accumulation: thread = dim, fp16 shadow-table gathers ----
    float a1 = 0.f, a2 = 0.f;
    const char* ieb = reinterpret_cast<const char*>(g_ieh) + tid * 2;
#pragma unroll 4
    for (int l4 = 0; l4 < LL / 4; ++l4) {
        float4 w1 = *reinterpret_cast<const float4*>(&sW1[l4 * 4]);
        float4 w2 = *reinterpret_cast<const float4*>(&sW2[l4 * 4]);
        int4   rr = *reinterpret_cast<const int4*>(&sOffH[l4 * 4]);
        float v0 = __half2float(*reinterpret_cast<const __half*>(
            ieb + (size_t)(uint32_t)rr.x));
        float v1 = __half2float(*reinterpret_cast<const __half*>(
            ieb + (size_t)(uint32_t)rr.y));
        float v2 = __half2float(*reinterpret_cast<const __half*>(
            ieb + (size_t)(uint32_t)rr.z));
        float v3 = __half2float(*reinterpret_cast<const __half*>(
            ieb + (size_t)(uint32_t)rr.w));
        a1 = fmaf(w1.x, v0, a1); a2 = fmaf(w2.x, v0, a2);
        a1 = fmaf(w1.y, v1, a1); a2 = fmaf(w2.y, v1, a2);
        a1 = fmaf(w1.z, v2, a1); a2 = fmaf(w2.z, v2, a2);
        a1 = fmaf(w1.w, v3, a1); a2 = fmaf(w2.w, v3, a2);
    }
    a1 *= i1; a2 *= i2;

    // ---- epilogue: 2x single-pass layernorm + GMF fuse + head ----
    float pu = a1 * sQ[tid];
    float pi = a2 * __ldg(&item_emb[(size_t)t * DD + tid]);   // target row fp32
    float su = pu, squ = pu * pu, si = pi, sqi = pi * pi;
    block_sum4(su, squ, si, sqi, sRed);
    float mu_  = su * (1.f / DD);
    float var  = squ * (1.f / DD) - mu_ * mu_;
    float mi_  = si * (1.f / DD);
    float var2 = sqi * (1.f / DD) - mi_ * mi_;
    float us = fmaf((pu - mu_) * rsqrtf(var + 1e-5f),  ln_u_g[tid], ln_u_b[tid]);
    float is = fmaf((pi - mi_) * rsqrtf(var2 + 1e-5f), ln_i_g[tid], ln_i_b[tid]);

    float tot = block_sum1(us * is * pred_W[tid], sRed);
    if (tid == 0) out[b] = tot + pred_b[0];

    // ---- last-block deterministic KL finalize ----
    if (out_idx >= 0) {
        if (tid == 0) {
            __threadfence();
            sLast = (atomicAdd(&g_ctr, 1) == B - 1);
        }
        __syncthreads();
        if (sLast) {
            __threadfence();
            float k = 0.f, n = 0.f;
            for (int i = tid; i < B; i += 128) { k += g_klsum[i]; n += g_nvalid[i]; }
            block_sum2(k, n, sRed);
            if (tid == 0) {
                out[out_idx] = 0.25f * k / fmaxf(n, 1.f);
                g_ctr = 0;
            }
        }
    }
}

// ---------------- launch ----------------------------------------------------
extern "C" void kernel_launch(void* const* d_in, const int* in_sizes, int n_in,
                              void* d_out, int out_size)
{
    const float* user_emb = (const float*)d_in[0];
    const float* item_emb = (const float*)d_in[1];
    const float* Wq       = (const float*)d_in[2];
    const float* Wk       = (const float*)d_in[3];
    const float* b_att    = (const float*)d_in[4];
    const float* v_att    = (const float*)d_in[5];
    const float* ln_u_g   = (const float*)d_in[6];
    const float* ln_u_b   = (const float*)d_in[7];
    const float* ln_i_g   = (const float*)d_in[8];
    const float* ln_i_b   = (const float*)d_in[9];
    const float* pred_W   = (const float*)d_in[10];
    const float* pred_b   = (const float*)d_in[11];
    const int*   user_hist= (const int*)d_in[12];
    const int*   user_idx = (const int*)d_in[13];
    const int*   item_idx = (const int*)d_in[14];

    int B      = in_sizes[13];
    int n_rows = in_sizes[1] / DD;      // 100001
    int pad_id = n_rows - 1;
    int out_idx = (out_size > B) ? (out_size - 1) : -1;
    int kwBlocks = (n_rows + 127) / 128;
    int qwBlocks = (B + 127) / 128;

    cudaFuncSetAttribute(gemm_kernel,
                         cudaFuncAttributeMaxDynamicSharedMemorySize,
                         GEMM_SMEM_BYTES);

    wkt_kernel<<<32, 256>>>(Wk, Wq);
    gemm_kernel<<<kwBlocks + qwBlocks, 256, GEMM_SMEM_BYTES>>>(
        item_emb, user_emb, b_att, user_idx, n_rows, B, kwBlocks);
    main_kernel<<<B, 128>>>(user_emb, item_emb, v_att,
                            ln_u_g, ln_u_b, ln_i_g, ln_i_b, pred_W, pred_b,
                            user_hist, user_idx, item_idx, (float*)d_out, pad_id,
                            B, out_idx);
}